// round 3
// baseline (speedup 1.0000x reference)
#include <cuda_runtime.h>
#include <math.h>

#define TAU 0.07f
#define EPSN 1e-12f

constexpr int B_   = 4;
constexpr int C_   = 256;
constexpr int K_   = 19;
constexpr int HW   = 65536;          // H*W = 256*256
constexpr int P    = B_ * HW;        // 262144 pixels
constexpr int TILE_Q = 64;           // pixels per tile in kA
constexpr int NTILES = P / TILE_Q;   // 4096
constexpr int NBLK_A = 296;          // 2 per SM
constexpr int NBLK_C = 1024;         // 1024*256 == P exactly
constexpr int KC   = K_ * C_;        // 4864
constexpr int TSTRIDE = 68;          // padded smem tile row stride (floats)

// ---- scratch (static __device__, no allocation) ----
__device__ float g_part[(size_t)NBLK_A * KC];  // per-block k0 partials
__device__ float g_npos[P];                    // positives per pixel
__device__ float g_k0n[KC];                    // normalized prototypes
__device__ float g_normk[K_];                  // k0n·k0 per class
__device__ int   g_nposblk[NBLK_A];            // per-block positive counts
__device__ float g_lsepart[NBLK_C];            // per-block npos*lse partials

// ============================================================
// Kernel A: fused rnorm + mask + k0 partial accumulation
//   grid 296 x 256 threads, dynamic smem ~75.5KB
// ============================================================
extern "C" __global__ void __launch_bounds__(256, 2)
kA(const float* __restrict__ feat, const float* __restrict__ gt)
{
    extern __shared__ float sm[];
    float* s_tile = sm;                         // [256][68]
    float* s_wk   = sm + C_ * TSTRIDE;          // [19][64]  (rn or 0 per (k,q))
    float* s_sq   = s_wk + K_ * TILE_Q;         // [4][64] ssq partials

    const int tid  = threadIdx.x;
    const int blk  = blockIdx.x;
    const int qof  = tid & 63;
    const int cgrp = tid >> 6;

    float acc[K_];
#pragma unroll
    for (int k = 0; k < K_; k++) acc[k] = 0.f;
    int np_acc = 0;

    for (int t = blk; t < NTILES; t += NBLK_A) {
        const int p0  = t * TILE_Q;
        const int b   = p0 >> 16;
        const int hw0 = p0 & 65535;
        const float* fb = feat + (size_t)b * C_ * HW + hw0;

        __syncthreads();  // protect smem from previous tile's compute

        // ---- stage tile (coalesced) + sumsq partial (this thread's q is fixed) ----
        float ssql = 0.f;
#pragma unroll 4
        for (int i = 0; i < (C_ * TILE_Q) / 256; i++) {   // 64 iterations
            const int c = cgrp + i * 4;
            const float v = __ldg(fb + (size_t)c * HW + qof);
            s_tile[c * TSTRIDE + qof] = v;
            ssql = fmaf(v, v, ssql);
        }
        s_sq[cgrp * 64 + qof] = ssql;
        __syncthreads();

        // ---- rnorm + gt mask -> weights (64 threads) ----
        if (tid < TILE_Q) {
            const int q = tid;
            const float ssq = s_sq[q] + s_sq[64 + q] + s_sq[128 + q] + s_sq[192 + q];
            const float rn  = 1.0f / fmaxf(sqrtf(ssq), EPSN);
            const float* gb = gt + (size_t)b * K_ * HW + hw0 + q;
            int np = 0;
#pragma unroll
            for (int k = 0; k < K_; k++) {
                const float g = __ldg(gb + (size_t)k * HW);
                const bool pos = (g == 1.0f);
                s_wk[k * TILE_Q + q] = pos ? rn : 0.f;
                np += pos ? 1 : 0;
            }
            g_npos[p0 + q] = (float)np;
            np_acc += np;
        }
        __syncthreads();

        // ---- compute: thread owns channel c = tid; clean FFMA inner loop ----
        const float* trow = s_tile + tid * TSTRIDE;
#pragma unroll 4
        for (int q4 = 0; q4 < TILE_Q / 4; q4++) {
            const float4 v = *(const float4*)(trow + q4 * 4);
#pragma unroll
            for (int k = 0; k < K_; k++) {
                const float4 w = *(const float4*)(s_wk + k * TILE_Q + q4 * 4);
                acc[k] = fmaf(v.x, w.x, acc[k]);
                acc[k] = fmaf(v.y, w.y, acc[k]);
                acc[k] = fmaf(v.z, w.z, acc[k]);
                acc[k] = fmaf(v.w, w.w, acc[k]);
            }
        }
    }

    // ---- emit per-block partials (deterministic, no atomics) ----
#pragma unroll
    for (int k = 0; k < K_; k++)
        g_part[(size_t)blk * KC + k * C_ + tid] = acc[k];

    __syncthreads();
    int* s_int = (int*)s_sq;
    if (tid < TILE_Q) s_int[tid] = np_acc;
    __syncthreads();
    if (tid == 0) {
        int s = 0;
        for (int i = 0; i < TILE_Q; i++) s += s_int[i];
        g_nposblk[blk] = s;
    }
}

// ============================================================
// Kernel B: reduce k0 partials -> k0n, per-class norms
//   grid 19 x 256 threads (block = class k, thread = channel c)
// ============================================================
extern "C" __global__ void kB()
{
    const int k = blockIdx.x;
    const int c = threadIdx.x;
    float v = 0.f;
    for (int b = 0; b < NBLK_A; b++)
        v += g_part[(size_t)b * KC + k * C_ + c];

    __shared__ float red[256];
    red[c] = v * v;
    __syncthreads();
    for (int s = 128; s > 0; s >>= 1) {
        if (c < s) red[c] += red[c + s];
        __syncthreads();
    }
    const float ssq = red[0];
    const float inv = 1.0f / fmaxf(sqrtf(ssq), EPSN);
    g_k0n[k * C_ + c] = v * inv;
    if (c == 0) g_normk[k] = ssq * inv;   // = k0n . k0
}

// ============================================================
// Kernel C: per-pixel logits + logsumexp, weighted by npos
//   grid 1024 x 256 threads, 1 pixel per thread
// ============================================================
extern "C" __global__ void __launch_bounds__(256)
kC(const float* __restrict__ feat)
{
    __shared__ float s_k0nT[C_ * 20];   // [c][k] padded to 20 for float4 loads
    const int tid = threadIdx.x;
    for (int idx = tid; idx < KC; idx += 256) {
        const int k = idx >> 8;      // idx / 256
        const int c = idx & 255;
        s_k0nT[c * 20 + k] = g_k0n[idx];
    }
    for (int c = tid; c < C_; c += 256) s_k0nT[c * 20 + 19] = 0.f;
    __syncthreads();

    const int p  = blockIdx.x * 256 + tid;
    const int b  = p >> 16;
    const int hw = p & 65535;
    const float* fp = feat + (size_t)b * C_ * HW + hw;

    float s[K_];
#pragma unroll
    for (int k = 0; k < K_; k++) s[k] = 0.f;
    float ssq = 0.f;

#pragma unroll 4
    for (int c = 0; c < C_; c++) {
        const float v = __ldg(fp + (size_t)c * HW);
        ssq = fmaf(v, v, ssq);
        const float4* row = (const float4*)(s_k0nT + c * 20);
        const float4 w0 = row[0], w1 = row[1], w2 = row[2], w3 = row[3], w4 = row[4];
        s[0]  = fmaf(w0.x, v, s[0]);  s[1]  = fmaf(w0.y, v, s[1]);
        s[2]  = fmaf(w0.z, v, s[2]);  s[3]  = fmaf(w0.w, v, s[3]);
        s[4]  = fmaf(w1.x, v, s[4]);  s[5]  = fmaf(w1.y, v, s[5]);
        s[6]  = fmaf(w1.z, v, s[6]);  s[7]  = fmaf(w1.w, v, s[7]);
        s[8]  = fmaf(w2.x, v, s[8]);  s[9]  = fmaf(w2.y, v, s[9]);
        s[10] = fmaf(w2.z, v, s[10]); s[11] = fmaf(w2.w, v, s[11]);
        s[12] = fmaf(w3.x, v, s[12]); s[13] = fmaf(w3.y, v, s[13]);
        s[14] = fmaf(w3.z, v, s[14]); s[15] = fmaf(w3.w, v, s[15]);
        s[16] = fmaf(w4.x, v, s[16]); s[17] = fmaf(w4.y, v, s[17]);
        s[18] = fmaf(w4.z, v, s[18]);
    }

    const float rnt = 1.0f / (fmaxf(sqrtf(ssq), EPSN) * TAU);
    float mx = -3.4e38f;
#pragma unroll
    for (int k = 0; k < K_; k++) {
        s[k] *= rnt;
        mx = fmaxf(mx, s[k]);
    }
    float sum = 0.f;
#pragma unroll
    for (int k = 0; k < K_; k++) sum += expf(s[k] - mx);
    const float lse = mx + logf(sum);

    const float contrib = g_npos[p] * lse;

    __shared__ float red[256];
    red[tid] = contrib;
    __syncthreads();
    for (int st = 128; st > 0; st >>= 1) {
        if (tid < st) red[tid] += red[tid + st];
        __syncthreads();
    }
    if (tid == 0) g_lsepart[blockIdx.x] = red[0];
}

// ============================================================
// Kernel D: final scalar loss
// ============================================================
extern "C" __global__ void kD(float* __restrict__ out)
{
    __shared__ float red[256];
    __shared__ int   redi[256];
    const int tid = threadIdx.x;

    float a = 0.f;
    for (int i = tid; i < NBLK_C; i += 256) a += g_lsepart[i];
    float nk = 0.f;
    if (tid < K_) nk = g_normk[tid];
    int np = 0;
    for (int i = tid; i < NBLK_A; i += 256) np += g_nposblk[i];

    red[tid]  = a - nk * (1.0f / TAU);
    redi[tid] = np;
    __syncthreads();
    for (int s = 128; s > 0; s >>= 1) {
        if (tid < s) { red[tid] += red[tid + s]; redi[tid] += redi[tid + s]; }
        __syncthreads();
    }
    if (tid == 0) out[0] = red[0] / (float)redi[0];
}

// ============================================================
// launch
// ============================================================
extern "C" void kernel_launch(void* const* d_in, const int* in_sizes, int n_in,
                              void* d_out, int out_size)
{
    const float* feat = (const float*)d_in[0];
    const float* gt   = (const float*)d_in[1];
    float* out        = (float*)d_out;

    const int smemA = (C_ * TSTRIDE + K_ * TILE_Q + 256) * (int)sizeof(float); // 75520
    cudaFuncSetAttribute(kA, cudaFuncAttributeMaxDynamicSharedMemorySize, smemA);

    kA<<<NBLK_A, 256, smemA>>>(feat, gt);
    kB<<<K_, 256>>>();
    kC<<<NBLK_C, 256>>>(feat);
    kD<<<1, 256>>>(out);
}